// round 10
// baseline (speedup 1.0000x reference)
#include <cuda_runtime.h>

#define ALPHA 0.2f
#define MASKV -9000000000000000.0f
using ull  = unsigned long long;
using ull2 = ulonglong2;

__constant__ __align__(16) float cW1[96];     // (3,1,32)
__constant__ __align__(16) float cA1[192];    // (3,64,1)
__constant__ __align__(16) float cW2[4608];   // (3,96,16)
__constant__ __align__(16) float cA2[96];     // (3,32,1)
__constant__ __align__(16) float cWp1[1152];  // (48,24)
__constant__ __align__(16) float cBp1[24];
__constant__ __align__(16) float cWp2[24];
__constant__ __align__(16) float cBp2[4];
__constant__ __align__(16) float cAdj[84];

#define NTHR 128
#define MAXBLK 1024
#define NT (MAXBLK*NTHR)

__device__ float    g_c12[6];                 // c1[3], c2[3]
__device__ unsigned g_mrow[9];                // adjacency bitmask per row
__device__ ull2     g_wh[(size_t)108 * NT];   // Wh pairs: [row][head][4] ull2
__device__ ull2     g_h2[(size_t)108 * NT];   // h2 pairs: [row][head][4] ull2
__device__ ull      g_f [(size_t)27  * NT];   // {f1,f2}[H*9+row]

__device__ __forceinline__ void ffma2(ull& d, ull a, ull b) {
    asm("fma.rn.f32x2 %0, %1, %2, %0;" : "+l"(d) : "l"(a), "l"(b));
}
__device__ __forceinline__ ull dup2(float x) {
    ull r; asm("mov.b64 %0, {%1, %1};" : "=l"(r) : "f"(x)); return r;
}
__device__ __forceinline__ ull pack2(float x, float y) {
    ull r; asm("mov.b64 %0, {%1, %2};" : "=l"(r) : "f"(x), "f"(y)); return r;
}
__device__ __forceinline__ float2 unp(ull v) {
    float2 r; asm("mov.b64 {%0, %1}, %2;" : "=f"(r.x), "=f"(r.y) : "l"(v)); return r;
}
__device__ __forceinline__ float tanh_fast(float x) {
    float r; asm("tanh.approx.f32 %0, %1;" : "=f"(r) : "f"(x)); return r;
}
__device__ __forceinline__ ull c64(const float* p) {
    return __double_as_longlong(*(const double*)(const void*)p);
}
__device__ __forceinline__ float lrelu(float x) { return fmaxf(x, ALPHA * x); }
__device__ __forceinline__ float elu(float x) {
    return (x > 0.f) ? x : (__expf(x) - 1.f);
}

__global__ void prep_kernel() {
    int t = threadIdx.x;
    if (t < 6) {
        int h = t % 3, half = t / 3;
        float s = 0.f;
        #pragma unroll
        for (int d = 0; d < 32; d++)
            s += cW1[h*32 + d] * cA1[h*64 + half*32 + d];
        g_c12[half*3 + h] = s;
    }
    if (t < 9) {
        unsigned m = 0;
        for (int j = 0; j < 9; j++)
            if (cAdj[t*9 + j] > 0.f) m |= (1u << j);
        g_mrow[t] = m;
    }
}

// GEMM pass: NR rows x ALL 3 heads; each elu computed exactly once per (k,row).
template<int NR>
__device__ __forceinline__ void gemm3h(const float* __restrict__ sTp, int r0,
                                       ull2* __restrict__ whb, ull* __restrict__ fb)
{
    ull acc[NR][3][8];
    #pragma unroll
    for (int r = 0; r < NR; r++)
        #pragma unroll
        for (int H = 0; H < 3; H++)
            #pragma unroll
            for (int p = 0; p < 8; p++) acc[r][H][p] = 0ull;

    #pragma unroll 1
    for (int kh = 0; kh < 3; kh++) {
        float s[NR];
        #pragma unroll
        for (int r = 0; r < NR; r++) s[r] = sTp[kh*9 + r0 + r];
        #pragma unroll 4
        for (int d = 0; d < 32; d++) {
            const int k = kh*32 + d;
            const float w1 = cW1[k];
            ull e[NR];
            #pragma unroll
            for (int r = 0; r < NR; r++) e[r] = dup2(elu(s[r] * w1));
            #pragma unroll
            for (int H = 0; H < 3; H++) {
                const float* wr = &cW2[H*1536 + k*16];
                const ull2 wa = *(const ull2*)(wr);
                const ull2 wb = *(const ull2*)(wr + 4);
                const ull2 wc = *(const ull2*)(wr + 8);
                const ull2 wd = *(const ull2*)(wr + 12);
                #pragma unroll
                for (int r = 0; r < NR; r++) {
                    ffma2(acc[r][H][0], e[r], wa.x); ffma2(acc[r][H][1], e[r], wa.y);
                    ffma2(acc[r][H][2], e[r], wb.x); ffma2(acc[r][H][3], e[r], wb.y);
                    ffma2(acc[r][H][4], e[r], wc.x); ffma2(acc[r][H][5], e[r], wc.y);
                    ffma2(acc[r][H][6], e[r], wd.x); ffma2(acc[r][H][7], e[r], wd.y);
                }
            }
        }
    }
    // epilogue: f1/f2 per (row, head) + 16B Wh stores
    #pragma unroll
    for (int r = 0; r < NR; r++) {
        #pragma unroll
        for (int H = 0; H < 3; H++) {
            float f1 = 0.f, f2 = 0.f;
            #pragma unroll
            for (int p = 0; p < 8; p++) {
                float2 t = unp(acc[r][H][p]);
                f1 += t.x * cA2[H*32 + 2*p]      + t.y * cA2[H*32 + 2*p + 1];
                f2 += t.x * cA2[H*32 + 16 + 2*p] + t.y * cA2[H*32 + 17 + 2*p];
            }
            fb[(H*9 + r0 + r)*NT] = pack2(f1, f2);
            #pragma unroll
            for (int q = 0; q < 4; q++) {
                ull2 v; v.x = acc[r][H][2*q]; v.y = acc[r][H][2*q + 1];
                whb[((r0 + r)*12 + H*4 + q)*NT] = v;
            }
        }
    }
}

// attention apply for NR rows of head H, j-outer (Wh tile loaded once per group)
template<int NR>
__device__ __forceinline__ void apply_grp(
    const float* __restrict__ f1, const float* __restrict__ f2,
    const unsigned* __restrict__ mrow,
    const ull2* __restrict__ whb, ull2* __restrict__ h2b, int H, int gi)
{
    float att[NR][9];
    #pragma unroll
    for (int r = 0; r < NR; r++) {
        const int i = gi + r;
        const unsigned m = mrow[i];
        const float f1i = f1[i];
        float e[9], mx = -3.0e38f;
        #pragma unroll
        for (int j = 0; j < 9; j++) {
            float x = lrelu(f1i + f2[j]);
            if (!((m >> j) & 1u)) x = MASKV;
            e[j] = x; mx = fmaxf(mx, x);
        }
        float den = 0.f;
        #pragma unroll
        for (int j = 0; j < 9; j++) { e[j] = __expf(e[j] - mx); den += e[j]; }
        const float inv = __fdividef(1.f, den);
        #pragma unroll
        for (int j = 0; j < 9; j++) att[r][j] = e[j] * inv;
    }

    ull h2a[NR][8];
    #pragma unroll
    for (int r = 0; r < NR; r++)
        #pragma unroll
        for (int p = 0; p < 8; p++) h2a[r][p] = 0ull;

    #pragma unroll
    for (int j = 0; j < 9; j++) {
        const ull2 w0 = whb[(j*12 + H*4 + 0)*NT];
        const ull2 w1 = whb[(j*12 + H*4 + 1)*NT];
        const ull2 w2 = whb[(j*12 + H*4 + 2)*NT];
        const ull2 w3 = whb[(j*12 + H*4 + 3)*NT];
        #pragma unroll
        for (int r = 0; r < NR; r++) {
            const ull wd = dup2(att[r][j]);
            ffma2(h2a[r][0], w0.x, wd); ffma2(h2a[r][1], w0.y, wd);
            ffma2(h2a[r][2], w1.x, wd); ffma2(h2a[r][3], w1.y, wd);
            ffma2(h2a[r][4], w2.x, wd); ffma2(h2a[r][5], w2.y, wd);
            ffma2(h2a[r][6], w3.x, wd); ffma2(h2a[r][7], w3.y, wd);
        }
    }
    #pragma unroll
    for (int r = 0; r < NR; r++)
        #pragma unroll
        for (int q = 0; q < 4; q++) {
            ull2 v; v.x = h2a[r][2*q]; v.y = h2a[r][2*q + 1];
            h2b[((gi + r)*12 + H*4 + q)*NT] = v;
        }
}

__global__ void __launch_bounds__(NTHR, 3)
gnn_main(const float* __restrict__ g_obs, float* __restrict__ g_out, int B)
{
    __shared__ float sS[NTHR * 29];   // per-thread s1[27] (stride 29, odd)

    const int tid  = threadIdx.x;
    const int gtid = blockIdx.x * NTHR + tid;
    const int stride = gridDim.x * NTHR;
    float* sTp = sS + tid * 29;
    ull2*  whb = g_wh + gtid;
    ull2*  h2b = g_h2 + gtid;
    ull*   fb  = g_f  + gtid;

    unsigned mrow[9];
    #pragma unroll
    for (int i = 0; i < 9; i++) mrow[i] = __ldg(&g_mrow[i]);
    float c1r[3], c2r[3];
    #pragma unroll
    for (int h = 0; h < 3; h++) { c1r[h] = __ldg(&g_c12[h]); c2r[h] = __ldg(&g_c12[3+h]); }

    for (int b = gtid; b < B; b += stride) {

        // ================= layer-1 (rank-1 collapse): s1[h][i] =================
        {
            float og[9];
            #pragma unroll
            for (int n = 0; n < 9; n++) og[n] = g_obs[b*9 + n];
            #pragma unroll 1
            for (int h = 0; h < 3; h++) {
                const float c1h = c1r[h], c2h = c2r[h];
                float gg[9];
                #pragma unroll
                for (int j = 0; j < 9; j++) gg[j] = c2h * og[j];
                #pragma unroll
                for (int i = 0; i < 9; i++) {
                    const unsigned m = mrow[i];
                    const float fi = c1h * og[i];
                    float e[9], mx = -3.0e38f;
                    #pragma unroll
                    for (int j = 0; j < 9; j++) {
                        float x = lrelu(fi + gg[j]);
                        if (!((m >> j) & 1u)) x = MASKV;
                        e[j] = x; mx = fmaxf(mx, x);
                    }
                    float den = 0.f, num = 0.f;
                    #pragma unroll
                    for (int j = 0; j < 9; j++) {
                        float p = __expf(e[j] - mx);
                        den += p; num += p * og[j];
                    }
                    sTp[h*9 + i] = __fdividef(num, den);
                }
            }
        }

        // ================= GEMM: 2-row x 3-head passes =================
        gemm3h<2>(sTp, 0, whb, fb);
        gemm3h<2>(sTp, 2, whb, fb);
        gemm3h<2>(sTp, 4, whb, fb);
        gemm3h<2>(sTp, 6, whb, fb);
        gemm3h<1>(sTp, 8, whb, fb);

        // ================= attention apply per head, 2-row groups =================
        #pragma unroll 1
        for (int H = 0; H < 3; H++) {
            float f1[9], f2[9];
            #pragma unroll
            for (int j = 0; j < 9; j++) {
                float2 t = unp(fb[(H*9 + j)*NT]);
                f1[j] = t.x; f2[j] = t.y;
            }
            apply_grp<2>(f1, f2, mrow, whb, h2b, H, 0);
            apply_grp<2>(f1, f2, mrow, whb, h2b, H, 2);
            apply_grp<2>(f1, f2, mrow, whb, h2b, H, 4);
            apply_grp<2>(f1, f2, mrow, whb, h2b, H, 6);
            apply_grp<1>(f1, f2, mrow, whb, h2b, H, 8);
        }

        // ================= pooling scores (16B h2 loads) =================
        float scl[9];
        #pragma unroll 1
        for (int n = 0; n < 9; n++) {
            ull U[12];
            #pragma unroll
            for (int mp = 0; mp < 12; mp++) U[mp] = c64(&cBp1[2*mp]);
            #pragma unroll 2
            for (int m2 = 0; m2 < 12; m2++) {
                const ull2 hv2 = h2b[(n*12 + m2)*NT];
                const float2 ha = unp(hv2.x);
                const float2 hb = unp(hv2.y);
                const ull hx0 = dup2(ha.x), hx1 = dup2(ha.y);
                const ull hy0 = dup2(hb.x), hy1 = dup2(hb.y);
                #pragma unroll
                for (int mq = 0; mq < 6; mq++) {
                    const ull2 w0 = *(const ull2*)&cWp1[(4*m2    )*24 + 4*mq];
                    const ull2 w1 = *(const ull2*)&cWp1[(4*m2 + 1)*24 + 4*mq];
                    const ull2 w2 = *(const ull2*)&cWp1[(4*m2 + 2)*24 + 4*mq];
                    const ull2 w3 = *(const ull2*)&cWp1[(4*m2 + 3)*24 + 4*mq];
                    ffma2(U[2*mq],     hx0, w0.x); ffma2(U[2*mq + 1], hx0, w0.y);
                    ffma2(U[2*mq],     hx1, w1.x); ffma2(U[2*mq + 1], hx1, w1.y);
                    ffma2(U[2*mq],     hy0, w2.x); ffma2(U[2*mq + 1], hy0, w2.y);
                    ffma2(U[2*mq],     hy1, w3.x); ffma2(U[2*mq + 1], hy1, w3.y);
                }
            }
            float s = cBp2[0];
            #pragma unroll
            for (int mp = 0; mp < 12; mp++) {
                float2 u = unp(U[mp]);
                s += tanh_fast(u.x) * cWp2[2*mp] + tanh_fast(u.y) * cWp2[2*mp + 1];
            }
            scl[n] = s;
        }

        // softmax over nodes
        float mx = scl[0];
        #pragma unroll
        for (int n = 1; n < 9; n++) mx = fmaxf(mx, scl[n]);
        float den = 0.f, wnl[9];
        #pragma unroll
        for (int n = 0; n < 9; n++) { float p = __expf(scl[n] - mx); wnl[n] = p; den += p; }
        const float iv = __fdividef(1.f, den);

        // weighted sum + 16B stores
        ull2 op[12];
        #pragma unroll
        for (int p = 0; p < 12; p++) { op[p].x = 0ull; op[p].y = 0ull; }
        #pragma unroll 1
        for (int n = 0; n < 9; n++) {
            const ull wd = dup2(wnl[n] * iv);
            #pragma unroll
            for (int p = 0; p < 12; p++) {
                const ull2 h = h2b[(n*12 + p)*NT];
                ffma2(op[p].x, h.x, wd);
                ffma2(op[p].y, h.y, wd);
            }
        }
        #pragma unroll
        for (int p = 0; p < 12; p++)
            *(ull2*)&g_out[(size_t)b*48 + 4*p] = op[p];
    }
}

extern "C" void kernel_launch(void* const* d_in, const int* in_sizes, int n_in,
                              void* d_out, int out_size) {
    const float* obs = (const float*)d_in[0];
    int B = in_sizes[0] / 9;

    cudaMemcpyToSymbolAsync(cAdj, d_in[1],   81 * 4, 0, cudaMemcpyDeviceToDevice);
    cudaMemcpyToSymbolAsync(cW1,  d_in[2],   96 * 4, 0, cudaMemcpyDeviceToDevice);
    cudaMemcpyToSymbolAsync(cA1,  d_in[3],  192 * 4, 0, cudaMemcpyDeviceToDevice);
    cudaMemcpyToSymbolAsync(cW2,  d_in[4], 4608 * 4, 0, cudaMemcpyDeviceToDevice);
    cudaMemcpyToSymbolAsync(cA2,  d_in[5],   96 * 4, 0, cudaMemcpyDeviceToDevice);
    cudaMemcpyToSymbolAsync(cWp1, d_in[6], 1152 * 4, 0, cudaMemcpyDeviceToDevice);
    cudaMemcpyToSymbolAsync(cBp1, d_in[7],   24 * 4, 0, cudaMemcpyDeviceToDevice);
    cudaMemcpyToSymbolAsync(cWp2, d_in[8],   24 * 4, 0, cudaMemcpyDeviceToDevice);
    cudaMemcpyToSymbolAsync(cBp2, d_in[9],    1 * 4, 0, cudaMemcpyDeviceToDevice);

    int blocks = (B + NTHR - 1) / NTHR;
    if (blocks > MAXBLK) blocks = MAXBLK;

    prep_kernel<<<1, 32>>>();
    gnn_main<<<blocks, NTHR>>>(obs, (float*)d_out, B);
}

// round 12
// speedup vs baseline: 1.0841x; 1.0841x over previous
#include <cuda_runtime.h>

#define ALPHA 0.2f
#define MASKV -9000000000000000.0f
using ull  = unsigned long long;
using ull2 = ulonglong2;

__constant__ __align__(16) float cW1[96];     // (3,1,32)
__constant__ __align__(16) float cA1[192];    // (3,64,1)
__constant__ __align__(16) float cW2[4608];   // (3,96,16)
__constant__ __align__(16) float cA2[96];     // (3,32,1)
__constant__ __align__(16) float cWp1[1152];  // (48,24)
__constant__ __align__(16) float cBp1[24];
__constant__ __align__(16) float cWp2[24];
__constant__ __align__(16) float cBp2[4];
__constant__ __align__(16) float cAdj[84];

#define NTHR 128
#define MAXBLK 1024
#define NT (MAXBLK*NTHR)
#define SSTR 83   // per-thread smem floats: [0..26]=s1, [27..80]=f1/f2 pairs

__device__ float    g_c12[6];                 // c1[3], c2[3]
__device__ unsigned g_mrow[9];                // adjacency bitmask per row
__device__ ull2     g_wh[(size_t)108 * NT];   // Wh pairs: [row][H*4+q] ull2
__device__ ull2     g_h2[(size_t)108 * NT];   // h2 pairs: [row][12] ull2

__device__ __forceinline__ void ffma2(ull& d, ull a, ull b) {
    asm("fma.rn.f32x2 %0, %1, %2, %0;" : "+l"(d) : "l"(a), "l"(b));
}
__device__ __forceinline__ ull dup2(float x) {
    ull r; asm("mov.b64 %0, {%1, %1};" : "=l"(r) : "f"(x)); return r;
}
__device__ __forceinline__ float2 unp(ull v) {
    float2 r; asm("mov.b64 {%0, %1}, %2;" : "=f"(r.x), "=f"(r.y) : "l"(v)); return r;
}
__device__ __forceinline__ float tanh_fast(float x) {
    float r; asm("tanh.approx.f32 %0, %1;" : "=f"(r) : "f"(x)); return r;
}
__device__ __forceinline__ ull c64(const float* p) {
    return __double_as_longlong(*(const double*)(const void*)p);
}
__device__ __forceinline__ float lrelu(float x) { return fmaxf(x, ALPHA * x); }
__device__ __forceinline__ float elu(float x) {
    return (x > 0.f) ? x : (__expf(x) - 1.f);
}

__global__ void prep_kernel() {
    int t = threadIdx.x;
    if (t < 6) {
        int h = t % 3, half = t / 3;
        float s = 0.f;
        #pragma unroll
        for (int d = 0; d < 32; d++)
            s += cW1[h*32 + d] * cA1[h*64 + half*32 + d];
        g_c12[half*3 + h] = s;
    }
    if (t < 9) {
        unsigned m = 0;
        for (int j = 0; j < 9; j++)
            if (cAdj[t*9 + j] > 0.f) m |= (1u << j);
        g_mrow[t] = m;
    }
}

// GEMM pass: 3 rows x 3 heads x 8 columns (half C). elu per (k,row) once per half.
template<int C>
__device__ __forceinline__ void gemm_half(const float* __restrict__ sTp,
                                          float* __restrict__ fT,
                                          int g3, ull2* __restrict__ whb)
{
    ull acc[3][3][4];
    #pragma unroll
    for (int r = 0; r < 3; r++)
        #pragma unroll
        for (int H = 0; H < 3; H++)
            #pragma unroll
            for (int p = 0; p < 4; p++) acc[r][H][p] = 0ull;

    #pragma unroll 1
    for (int kh = 0; kh < 3; kh++) {
        const float s0 = sTp[kh*9 + g3];
        const float s1 = sTp[kh*9 + g3 + 1];
        const float s2 = sTp[kh*9 + g3 + 2];
        #pragma unroll 2
        for (int d = 0; d < 32; d++) {
            const int k = kh*32 + d;
            const float w1 = cW1[k];
            ull e[3];
            e[0] = dup2(elu(s0 * w1));
            e[1] = dup2(elu(s1 * w1));
            e[2] = dup2(elu(s2 * w1));
            #pragma unroll
            for (int H = 0; H < 3; H++) {
                const float* wr = &cW2[H*1536 + k*16 + C*8];
                const ull2 wa = *(const ull2*)(wr);
                const ull2 wb = *(const ull2*)(wr + 4);
                #pragma unroll
                for (int r = 0; r < 3; r++) {
                    ffma2(acc[r][H][0], e[r], wa.x);
                    ffma2(acc[r][H][1], e[r], wa.y);
                    ffma2(acc[r][H][2], e[r], wb.x);
                    ffma2(acc[r][H][3], e[r], wb.y);
                }
            }
        }
    }
    // epilogue: partial f1/f2 into SMEM + Wh stores (16B)
    #pragma unroll
    for (int r = 0; r < 3; r++) {
        #pragma unroll
        for (int H = 0; H < 3; H++) {
            float f1p = 0.f, f2p = 0.f;
            #pragma unroll
            for (int p = 0; p < 4; p++) {
                float2 t = unp(acc[r][H][p]);
                const int idx = H*32 + C*8 + 2*p;
                f1p += t.x * cA2[idx]      + t.y * cA2[idx + 1];
                f2p += t.x * cA2[idx + 16] + t.y * cA2[idx + 17];
            }
            const int fi = 27 + 2*(H*9 + g3 + r);
            if (C == 0) { fT[fi] = f1p;  fT[fi + 1] = f2p; }
            else        { fT[fi] += f1p; fT[fi + 1] += f2p; }
            ull2 v0; v0.x = acc[r][H][0]; v0.y = acc[r][H][1];
            ull2 v1; v1.x = acc[r][H][2]; v1.y = acc[r][H][3];
            whb[((g3 + r)*12 + H*4 + C*2 + 0)*NT] = v0;
            whb[((g3 + r)*12 + H*4 + C*2 + 1)*NT] = v1;
        }
    }
}

// attention apply: NR rows of head H, j-outer (Wh tile loaded once per group)
template<int NR>
__device__ __forceinline__ void apply_grp(
    const float* __restrict__ f1, const float* __restrict__ f2,
    const unsigned* __restrict__ mrow,
    const ull2* __restrict__ whb, ull2* __restrict__ h2b, int H, int gi)
{
    float att[NR][9];
    #pragma unroll
    for (int r = 0; r < NR; r++) {
        const int i = gi + r;
        const unsigned m = mrow[i];
        const float f1i = f1[i];
        float e[9], mx = -3.0e38f;
        #pragma unroll
        for (int j = 0; j < 9; j++) {
            float x = lrelu(f1i + f2[j]);
            if (!((m >> j) & 1u)) x = MASKV;
            e[j] = x; mx = fmaxf(mx, x);
        }
        float den = 0.f;
        #pragma unroll
        for (int j = 0; j < 9; j++) { e[j] = __expf(e[j] - mx); den += e[j]; }
        const float inv = __fdividef(1.f, den);
        #pragma unroll
        for (int j = 0; j < 9; j++) att[r][j] = e[j] * inv;
    }

    ull h2a[NR][8];
    #pragma unroll
    for (int r = 0; r < NR; r++)
        #pragma unroll
        for (int p = 0; p < 8; p++) h2a[r][p] = 0ull;

    #pragma unroll
    for (int j = 0; j < 9; j++) {
        const ull2 w0 = whb[(j*12 + H*4 + 0)*NT];
        const ull2 w1 = whb[(j*12 + H*4 + 1)*NT];
        const ull2 w2 = whb[(j*12 + H*4 + 2)*NT];
        const ull2 w3 = whb[(j*12 + H*4 + 3)*NT];
        #pragma unroll
        for (int r = 0; r < NR; r++) {
            const ull wd = dup2(att[r][j]);
            ffma2(h2a[r][0], w0.x, wd); ffma2(h2a[r][1], w0.y, wd);
            ffma2(h2a[r][2], w1.x, wd); ffma2(h2a[r][3], w1.y, wd);
            ffma2(h2a[r][4], w2.x, wd); ffma2(h2a[r][5], w2.y, wd);
            ffma2(h2a[r][6], w3.x, wd); ffma2(h2a[r][7], w3.y, wd);
        }
    }
    #pragma unroll
    for (int r = 0; r < NR; r++)
        #pragma unroll
        for (int q = 0; q < 4; q++) {
            ull2 v; v.x = h2a[r][2*q]; v.y = h2a[r][2*q + 1];
            h2b[((gi + r)*12 + H*4 + q)*NT] = v;
        }
}

__global__ void __launch_bounds__(NTHR, 4)
gnn_main(const float* __restrict__ g_obs, float* __restrict__ g_out, int B)
{
    __shared__ float sS[NTHR * SSTR];

    const int tid  = threadIdx.x;
    const int gtid = blockIdx.x * NTHR + tid;
    const int stride = gridDim.x * NTHR;
    float* sTp = sS + tid * SSTR;
    ull2*  whb = g_wh + gtid;
    ull2*  h2b = g_h2 + gtid;

    unsigned mrow[9];
    #pragma unroll
    for (int i = 0; i < 9; i++) mrow[i] = __ldg(&g_mrow[i]);
    float c1r[3], c2r[3];
    #pragma unroll
    for (int h = 0; h < 3; h++) { c1r[h] = __ldg(&g_c12[h]); c2r[h] = __ldg(&g_c12[3+h]); }

    for (int b = gtid; b < B; b += stride) {

        // ================= layer-1 (rank-1 collapse): s1[h][i] =================
        {
            float og[9];
            #pragma unroll
            for (int n = 0; n < 9; n++) og[n] = g_obs[b*9 + n];
            #pragma unroll 1
            for (int h = 0; h < 3; h++) {
                const float c1h = c1r[h], c2h = c2r[h];
                float gg[9];
                #pragma unroll
                for (int j = 0; j < 9; j++) gg[j] = c2h * og[j];
                #pragma unroll
                for (int i = 0; i < 9; i++) {
                    const unsigned m = mrow[i];
                    const float fi = c1h * og[i];
                    float e[9], mx = -3.0e38f;
                    #pragma unroll
                    for (int j = 0; j < 9; j++) {
                        float x = lrelu(fi + gg[j]);
                        if (!((m >> j) & 1u)) x = MASKV;
                        e[j] = x; mx = fmaxf(mx, x);
                    }
                    float den = 0.f, num = 0.f;
                    #pragma unroll
                    for (int j = 0; j < 9; j++) {
                        float p = __expf(e[j] - mx);
                        den += p; num += p * og[j];
                    }
                    sTp[h*9 + i] = __fdividef(num, den);
                }
            }
        }

        // ================= GEMM: 3 row-groups x 2 column halves =================
        #pragma unroll 1
        for (int g3 = 0; g3 < 9; g3 += 3) {
            gemm_half<0>(sTp, sTp, g3, whb);
            gemm_half<1>(sTp, sTp, g3, whb);
        }

        // ================= attention apply per head (f from SMEM) =================
        #pragma unroll 1
        for (int H = 0; H < 3; H++) {
            float f1[9], f2[9];
            #pragma unroll
            for (int j = 0; j < 9; j++) {
                f1[j] = sTp[27 + 2*(H*9 + j)];
                f2[j] = sTp[28 + 2*(H*9 + j)];
            }
            apply_grp<2>(f1, f2, mrow, whb, h2b, H, 0);
            apply_grp<2>(f1, f2, mrow, whb, h2b, H, 2);
            apply_grp<2>(f1, f2, mrow, whb, h2b, H, 4);
            apply_grp<2>(f1, f2, mrow, whb, h2b, H, 6);
            apply_grp<1>(f1, f2, mrow, whb, h2b, H, 8);
        }

        // ================= pooling scores (16B h2 loads) =================
        float scl[9];
        #pragma unroll 1
        for (int n = 0; n < 9; n++) {
            ull U[12];
            #pragma unroll
            for (int mp = 0; mp < 12; mp++) U[mp] = c64(&cBp1[2*mp]);
            #pragma unroll 2
            for (int m2 = 0; m2 < 12; m2++) {
                const ull2 hv2 = h2b[(n*12 + m2)*NT];
                const float2 ha = unp(hv2.x);
                const float2 hb = unp(hv2.y);
                const ull hx0 = dup2(ha.x), hx1 = dup2(ha.y);
                const ull hy0 = dup2(hb.x), hy1 = dup2(hb.y);
                #pragma unroll
                for (int mq = 0; mq < 6; mq++) {
                    const ull2 w0 = *(const ull2*)&cWp1[(4*m2    )*24 + 4*mq];
                    const ull2 w1 = *(const ull2*)&cWp1[(4*m2 + 1)*24 + 4*mq];
                    const ull2 w2 = *(const ull2*)&cWp1[(4*m2 + 2)*24 + 4*mq];
                    const ull2 w3 = *(const ull2*)&cWp1[(4*m2 + 3)*24 + 4*mq];
                    ffma2(U[2*mq],     hx0, w0.x); ffma2(U[2*mq + 1], hx0, w0.y);
                    ffma2(U[2*mq],     hx1, w1.x); ffma2(U[2*mq + 1], hx1, w1.y);
                    ffma2(U[2*mq],     hy0, w2.x); ffma2(U[2*mq + 1], hy0, w2.y);
                    ffma2(U[2*mq],     hy1, w3.x); ffma2(U[2*mq + 1], hy1, w3.y);
                }
            }
            float s = cBp2[0];
            #pragma unroll
            for (int mp = 0; mp < 12; mp++) {
                float2 u = unp(U[mp]);
                s += tanh_fast(u.x) * cWp2[2*mp] + tanh_fast(u.y) * cWp2[2*mp + 1];
            }
            scl[n] = s;
        }

        // softmax over nodes
        float mx = scl[0];
        #pragma unroll
        for (int n = 1; n < 9; n++) mx = fmaxf(mx, scl[n]);
        float den = 0.f, wnl[9];
        #pragma unroll
        for (int n = 0; n < 9; n++) { float p = __expf(scl[n] - mx); wnl[n] = p; den += p; }
        const float iv = __fdividef(1.f, den);

        // weighted sum + 16B stores
        ull2 op[12];
        #pragma unroll
        for (int p = 0; p < 12; p++) { op[p].x = 0ull; op[p].y = 0ull; }
        #pragma unroll 1
        for (int n = 0; n < 9; n++) {
            const ull wd = dup2(wnl[n] * iv);
            #pragma unroll
            for (int p = 0; p < 12; p++) {
                const ull2 h = h2b[(n*12 + p)*NT];
                ffma2(op[p].x, h.x, wd);
                ffma2(op[p].y, h.y, wd);
            }
        }
        #pragma unroll
        for (int p = 0; p < 12; p++)
            *(ull2*)&g_out[(size_t)b*48 + 4*p] = op[p];
    }
}

extern "C" void kernel_launch(void* const* d_in, const int* in_sizes, int n_in,
                              void* d_out, int out_size) {
    const float* obs = (const float*)d_in[0];
    int B = in_sizes[0] / 9;

    cudaMemcpyToSymbolAsync(cAdj, d_in[1],   81 * 4, 0, cudaMemcpyDeviceToDevice);
    cudaMemcpyToSymbolAsync(cW1,  d_in[2],   96 * 4, 0, cudaMemcpyDeviceToDevice);
    cudaMemcpyToSymbolAsync(cA1,  d_in[3],  192 * 4, 0, cudaMemcpyDeviceToDevice);
    cudaMemcpyToSymbolAsync(cW2,  d_in[4], 4608 * 4, 0, cudaMemcpyDeviceToDevice);
    cudaMemcpyToSymbolAsync(cA2,  d_in[5],   96 * 4, 0, cudaMemcpyDeviceToDevice);
    cudaMemcpyToSymbolAsync(cWp1, d_in[6], 1152 * 4, 0, cudaMemcpyDeviceToDevice);
    cudaMemcpyToSymbolAsync(cBp1, d_in[7],   24 * 4, 0, cudaMemcpyDeviceToDevice);
    cudaMemcpyToSymbolAsync(cWp2, d_in[8],   24 * 4, 0, cudaMemcpyDeviceToDevice);
    cudaMemcpyToSymbolAsync(cBp2, d_in[9],    1 * 4, 0, cudaMemcpyDeviceToDevice);

    int blocks = (B + NTHR - 1) / NTHR;
    if (blocks > MAXBLK) blocks = MAXBLK;

    prep_kernel<<<1, 32>>>();
    gnn_main<<<blocks, NTHR>>>(obs, (float*)d_out, B);
}

// round 13
// speedup vs baseline: 1.7185x; 1.5851x over previous
#include <cuda_runtime.h>

#define ALPHA 0.2f
#define MASKV -9000000000000000.0f
using ull  = unsigned long long;
using ull2 = ulonglong2;

__constant__ __align__(16) float cW1[96];     // (3,1,32)
__constant__ __align__(16) float cA1[192];    // (3,64,1)
__constant__ __align__(16) float cW2[4608];   // (3,96,16)
__constant__ __align__(16) float cA2[96];     // (3,32,1)
__constant__ __align__(16) float cWp1[1152];  // (48,24)
__constant__ __align__(16) float cBp1[24];
__constant__ __align__(16) float cWp2[24];
__constant__ __align__(16) float cBp2[4];
__constant__ __align__(16) float cAdj[84];

#define NTHR 128
#define MAXBLK 1024

__device__ float    g_c12[6];                // c1[3], c2[3]
__device__ unsigned g_mrow[9];               // adjacency bitmask per row
// BLOCK-TILED scratch: per-block contiguous region, per-slot stride NTHR.
// A block's whole working set is ~0.3 MB (1-2 TLB pages) and every
// per-thread offset is a small immediate.
__device__ ull g_wh[(size_t)72  * NTHR * MAXBLK];  // Wh head tile: 9 rows x 8 pairs
__device__ ull g_h2[(size_t)216 * NTHR * MAXBLK];  // h2: 9 rows x 24 pairs

__device__ __forceinline__ void ffma2(ull& d, ull a, ull b) {
    asm("fma.rn.f32x2 %0, %1, %2, %0;" : "+l"(d) : "l"(a), "l"(b));
}
__device__ __forceinline__ ull dup2(float x) {
    ull r; asm("mov.b64 %0, {%1, %1};" : "=l"(r) : "f"(x)); return r;
}
__device__ __forceinline__ float2 unp(ull v) {
    float2 r; asm("mov.b64 {%0, %1}, %2;" : "=f"(r.x), "=f"(r.y) : "l"(v)); return r;
}
__device__ __forceinline__ float tanh_fast(float x) {
    float r; asm("tanh.approx.f32 %0, %1;" : "=f"(r) : "f"(x)); return r;
}
__device__ __forceinline__ ull c64(const float* p) {
    return __double_as_longlong(*(const double*)(const void*)p);
}
__device__ __forceinline__ float lrelu(float x) { return fmaxf(x, ALPHA * x); }
__device__ __forceinline__ float elu(float x) {
    return (x > 0.f) ? x : (__expf(x) - 1.f);
}

__global__ void prep_kernel() {
    int t = threadIdx.x;
    if (t < 6) {
        int h = t % 3, half = t / 3;
        float s = 0.f;
        #pragma unroll
        for (int d = 0; d < 32; d++)
            s += cW1[h*32 + d] * cA1[h*64 + half*32 + d];
        g_c12[half*3 + h] = s;
    }
    if (t < 9) {
        unsigned m = 0;
        for (int j = 0; j < 9; j++)
            if (cAdj[t*9 + j] > 0.f) m |= (1u << j);
        g_mrow[t] = m;
    }
}

__global__ void __launch_bounds__(NTHR, 4)
gnn_main(const float* __restrict__ g_obs, float* __restrict__ g_out, int B)
{
    __shared__ float sS[NTHR * 29];   // per-thread s1[27] (stride 29, odd)

    const int tid  = threadIdx.x;
    const int gtid = blockIdx.x * NTHR + tid;
    const int stride = gridDim.x * NTHR;
    float* sTp = sS + tid * 29;
    ull*   whb = g_wh + (size_t)blockIdx.x * (72*NTHR)  + tid;
    ull*   h2b = g_h2 + (size_t)blockIdx.x * (216*NTHR) + tid;

    unsigned mrow[9];
    #pragma unroll
    for (int i = 0; i < 9; i++) mrow[i] = __ldg(&g_mrow[i]);
    float c1r[3], c2r[3];
    #pragma unroll
    for (int h = 0; h < 3; h++) { c1r[h] = __ldg(&g_c12[h]); c2r[h] = __ldg(&g_c12[3+h]); }

    for (int b = gtid; b < B; b += stride) {

        // ================= layer-1 (rank-1 collapse): s1[h][i] =================
        {
            float og[9];
            #pragma unroll
            for (int n = 0; n < 9; n++) og[n] = g_obs[b*9 + n];
            #pragma unroll 1
            for (int h = 0; h < 3; h++) {
                const float c1h = c1r[h], c2h = c2r[h];
                float gg[9];
                #pragma unroll
                for (int j = 0; j < 9; j++) gg[j] = c2h * og[j];
                #pragma unroll
                for (int i = 0; i < 9; i++) {
                    const unsigned m = mrow[i];
                    const float fi = c1h * og[i];
                    float e[9], mx = -3.0e38f;
                    #pragma unroll
                    for (int j = 0; j < 9; j++) {
                        float x = lrelu(fi + gg[j]);
                        if (!((m >> j) & 1u)) x = MASKV;
                        e[j] = x; mx = fmaxf(mx, x);
                    }
                    float den = 0.f, num = 0.f;
                    #pragma unroll
                    for (int j = 0; j < 9; j++) {
                        float p = __expf(e[j] - mx);
                        den += p; num += p * og[j];
                    }
                    sTp[h*9 + i] = __fdividef(num, den);
                }
            }
        }

        // ================= layer-2 per head =================
        #pragma unroll 1
        for (int H = 0; H < 3; H++) {
            const float* wH = &cW2[H*1536];
            float f1a[9], f2a[9];

            // ---- GEMM in 3-row passes (W2 from constant, 16B loads) ----
            #pragma unroll 1
            for (int g3 = 0; g3 < 9; g3 += 3) {
                ull acc[3][8];
                #pragma unroll
                for (int r = 0; r < 3; r++)
                    #pragma unroll
                    for (int p = 0; p < 8; p++) acc[r][p] = 0ull;

                #pragma unroll 1
                for (int kh = 0; kh < 3; kh++) {
                    const float sA = sTp[kh*9 + g3];
                    const float sB = sTp[kh*9 + g3 + 1];
                    const float sC = sTp[kh*9 + g3 + 2];
                    #pragma unroll 4
                    for (int d = 0; d < 32; d++) {
                        const int k = kh*32 + d;
                        const float w1 = cW1[k];
                        const ull eA = dup2(elu(sA * w1));
                        const ull eB = dup2(elu(sB * w1));
                        const ull eC = dup2(elu(sC * w1));
                        const float* wr = wH + k*16;
                        const ull2 wa = *(const ull2*)(wr);
                        const ull2 wb = *(const ull2*)(wr + 4);
                        const ull2 wc = *(const ull2*)(wr + 8);
                        const ull2 wd = *(const ull2*)(wr + 12);
                        ffma2(acc[0][0], eA, wa.x); ffma2(acc[0][1], eA, wa.y);
                        ffma2(acc[0][2], eA, wb.x); ffma2(acc[0][3], eA, wb.y);
                        ffma2(acc[0][4], eA, wc.x); ffma2(acc[0][5], eA, wc.y);
                        ffma2(acc[0][6], eA, wd.x); ffma2(acc[0][7], eA, wd.y);
                        ffma2(acc[1][0], eB, wa.x); ffma2(acc[1][1], eB, wa.y);
                        ffma2(acc[1][2], eB, wb.x); ffma2(acc[1][3], eB, wb.y);
                        ffma2(acc[1][4], eB, wc.x); ffma2(acc[1][5], eB, wc.y);
                        ffma2(acc[1][6], eB, wd.x); ffma2(acc[1][7], eB, wd.y);
                        ffma2(acc[2][0], eC, wa.x); ffma2(acc[2][1], eC, wa.y);
                        ffma2(acc[2][2], eC, wb.x); ffma2(acc[2][3], eC, wb.y);
                        ffma2(acc[2][4], eC, wc.x); ffma2(acc[2][5], eC, wc.y);
                        ffma2(acc[2][6], eC, wd.x); ffma2(acc[2][7], eC, wd.y);
                    }
                }
                #pragma unroll
                for (int r = 0; r < 3; r++) {
                    float f1 = 0.f, f2 = 0.f;
                    #pragma unroll
                    for (int p = 0; p < 8; p++) {
                        float2 t = unp(acc[r][p]);
                        f1 += t.x * cA2[H*32 + 2*p]      + t.y * cA2[H*32 + 2*p + 1];
                        f2 += t.x * cA2[H*32 + 16 + 2*p] + t.y * cA2[H*32 + 17 + 2*p];
                    }
                    f1a[g3 + r] = f1;
                    f2a[g3 + r] = f2;
                    #pragma unroll
                    for (int p = 0; p < 8; p++)
                        whb[((g3 + r)*8 + p)*NTHR] = acc[r][p];
                }
            }

            // ---- attention apply for head H ----
            #pragma unroll 1
            for (int i = 0; i < 9; i++) {
                const unsigned m = mrow[i];
                const float f1i = f1a[i];
                float e[9], mx = -3.0e38f;
                #pragma unroll
                for (int j = 0; j < 9; j++) {
                    float x = lrelu(f1i + f2a[j]);
                    if (!((m >> j) & 1u)) x = MASKV;
                    e[j] = x; mx = fmaxf(mx, x);
                }
                float den = 0.f;
                #pragma unroll
                for (int j = 0; j < 9; j++) { e[j] = __expf(e[j] - mx); den += e[j]; }
                const float inv = __fdividef(1.f, den);

                ull h2a[8];
                #pragma unroll
                for (int p = 0; p < 8; p++) h2a[p] = 0ull;
                #pragma unroll
                for (int j = 0; j < 9; j++) {
                    const ull wd = dup2(e[j] * inv);
                    #pragma unroll
                    for (int p = 0; p < 8; p++)
                        ffma2(h2a[p], whb[(j*8 + p)*NTHR], wd);
                }
                #pragma unroll
                for (int p = 0; p < 8; p++)
                    h2b[(i*24 + H*8 + p)*NTHR] = h2a[p];
            }
        }

        // ================= pooling =================
        float scl[9];
        #pragma unroll 1
        for (int n = 0; n < 9; n++) {
            ull U[12];
            #pragma unroll
            for (int mp = 0; mp < 12; mp++) U[mp] = c64(&cBp1[2*mp]);
            #pragma unroll 4
            for (int cp = 0; cp < 24; cp++) {
                float2 hv = unp(h2b[(n*24 + cp)*NTHR]);
                ull hx = dup2(hv.x), hy = dup2(hv.y);
                #pragma unroll
                for (int mq = 0; mq < 6; mq++) {
                    ull2 wa = *(const ull2*)&cWp1[(2*cp    )*24 + 4*mq];
                    ull2 wb = *(const ull2*)&cWp1[(2*cp + 1)*24 + 4*mq];
                    ffma2(U[2*mq],     hx, wa.x);
                    ffma2(U[2*mq + 1], hx, wa.y);
                    ffma2(U[2*mq],     hy, wb.x);
                    ffma2(U[2*mq + 1], hy, wb.y);
                }
            }
            float s = cBp2[0];
            #pragma unroll
            for (int mp = 0; mp < 12; mp++) {
                float2 u = unp(U[mp]);
                s += tanh_fast(u.x) * cWp2[2*mp] + tanh_fast(u.y) * cWp2[2*mp + 1];
            }
            scl[n] = s;
        }

        // softmax over nodes
        float mx = scl[0];
        #pragma unroll
        for (int n = 1; n < 9; n++) mx = fmaxf(mx, scl[n]);
        float den = 0.f, wnl[9];
        #pragma unroll
        for (int n = 0; n < 9; n++) { float p = __expf(scl[n] - mx); wnl[n] = p; den += p; }
        const float iv = __fdividef(1.f, den);

        // weighted sum + stores
        ull outp[24];
        #pragma unroll
        for (int p = 0; p < 24; p++) outp[p] = 0ull;
        #pragma unroll 1
        for (int n = 0; n < 9; n++) {
            const ull wd = dup2(wnl[n] * iv);
            #pragma unroll
            for (int p = 0; p < 24; p++)
                ffma2(outp[p], h2b[(n*24 + p)*NTHR], wd);
        }
        #pragma unroll
        for (int p = 0; p < 24; p++)
            *(ull*)&g_out[(size_t)b*48 + 2*p] = outp[p];
    }
}

extern "C" void kernel_launch(void* const* d_in, const int* in_sizes, int n_in,
                              void* d_out, int out_size) {
    const float* obs = (const float*)d_in[0];
    int B = in_sizes[0] / 9;

    cudaMemcpyToSymbolAsync(cAdj, d_in[1],   81 * 4, 0, cudaMemcpyDeviceToDevice);
    cudaMemcpyToSymbolAsync(cW1,  d_in[2],   96 * 4, 0, cudaMemcpyDeviceToDevice);
    cudaMemcpyToSymbolAsync(cA1,  d_in[3],  192 * 4, 0, cudaMemcpyDeviceToDevice);
    cudaMemcpyToSymbolAsync(cW2,  d_in[4], 4608 * 4, 0, cudaMemcpyDeviceToDevice);
    cudaMemcpyToSymbolAsync(cA2,  d_in[5],   96 * 4, 0, cudaMemcpyDeviceToDevice);
    cudaMemcpyToSymbolAsync(cWp1, d_in[6], 1152 * 4, 0, cudaMemcpyDeviceToDevice);
    cudaMemcpyToSymbolAsync(cBp1, d_in[7],   24 * 4, 0, cudaMemcpyDeviceToDevice);
    cudaMemcpyToSymbolAsync(cWp2, d_in[8],   24 * 4, 0, cudaMemcpyDeviceToDevice);
    cudaMemcpyToSymbolAsync(cBp2, d_in[9],    1 * 4, 0, cudaMemcpyDeviceToDevice);

    int blocks = (B + NTHR - 1) / NTHR;
    if (blocks > MAXBLK) blocks = MAXBLK;

    prep_kernel<<<1, 32>>>();
    gnn_main<<<blocks, NTHR>>>(obs, (float*)d_out, B);
}